// round 15
// baseline (speedup 1.0000x reference)
#include <cuda_runtime.h>
#include <cuda_fp16.h>

#define IMG_H 1024
#define IMG_W 1024
#define IMG_HW (IMG_H * IMG_W)
#define WS 128
#define HALF 64
#define NE 6
#define NF 7
#define DH 16
#define NC 512
#define PX_PER_C (WS * WS)
#define PROB_ELEMS (NC * PX_PER_C)

#define THREADS 256          // 8 warps
#define BLOCKS_X 2           // 2 x 64 rows; each warp pipelines 8 rows
#define ROWS_PER_WARP 8
#define PADW 136             // h2 words per pair-plane; conflict-free LDS.128
#define PADF 128             // f32 stage plane stride
#define F32_PER_BUF (7 * PADF)         // 896
#define F32_PER_WARP (2 * F32_PER_BUF) // 1792
#define H2_PER_WARP (4 * PADW)         // 544
#define DSM_BYTES (8 * F32_PER_WARP * 4 + 8 * H2_PER_WARP * 4)  // 74752

// pack two f32 -> f16x2 (rn); first arg lands in the LOW half
__device__ __forceinline__ unsigned cvt2h(float lo, float hi) {
    unsigned r; asm("cvt.rn.f16x2.f32 %0, %1, %2;" : "=r"(r) : "f"(hi), "f"(lo)); return r;
}
__device__ __forceinline__ unsigned max2z(unsigned v) {
    unsigned r; asm("max.f16x2 %0, %1, %2;" : "=r"(r) : "r"(v), "r"(0u)); return r;
}
__device__ __forceinline__ void cp4(unsigned dst_sa, const float* src) {
    asm volatile("cp.async.ca.shared.global [%0], [%1], 4;" :: "r"(dst_sa), "l"(src));
}
// m16n8k8, all-f16
__device__ __forceinline__ void mma8h(unsigned& d0, unsigned& d1,
                                      unsigned a0, unsigned a1,
                                      unsigned b0,
                                      unsigned c0, unsigned c1) {
    asm volatile(
        "mma.sync.aligned.m16n8k8.row.col.f16.f16.f16.f16 "
        "{%0,%1}, {%2,%3}, {%4}, {%5,%6};"
        : "=r"(d0), "=r"(d1)
        : "r"(a0), "r"(a1), "r"(b0), "r"(c0), "r"(c1));
}
// m16n8k16, all-f16
__device__ __forceinline__ void mma16h(unsigned& d0, unsigned& d1,
                                       unsigned a0, unsigned a1, unsigned a2, unsigned a3,
                                       unsigned b0, unsigned b1,
                                       unsigned c0, unsigned c1) {
    asm volatile(
        "mma.sync.aligned.m16n8k16.row.col.f16.f16.f16.f16 "
        "{%0,%1}, {%2,%3,%4,%5}, {%6,%7}, {%8,%9};"
        : "=r"(d0), "=r"(d1)
        : "r"(a0), "r"(a1), "r"(a2), "r"(a3), "r"(b0), "r"(b1), "r"(c0), "r"(c1));
}
// m16n8k16, f16 in, f32 accumulate (final layer)
__device__ __forceinline__ void mma16f(float& d0, float& d1, float& d2, float& d3,
                                       unsigned a0, unsigned a1, unsigned a2, unsigned a3,
                                       unsigned b0, unsigned b1,
                                       float c0, float c1, float c2, float c3) {
    asm volatile(
        "mma.sync.aligned.m16n8k16.row.col.f32.f16.f16.f32 "
        "{%0,%1,%2,%3}, {%4,%5,%6,%7}, {%8,%9}, {%10,%11,%12,%13};"
        : "=f"(d0), "=f"(d1), "=f"(d2), "=f"(d3)
        : "r"(a0), "r"(a1), "r"(a2), "r"(a3), "r"(b0), "r"(b1),
          "f"(c0), "f"(c1), "f"(c2), "f"(c3));
}

__global__ __launch_bounds__(THREADS, 3)
void instanseg_kernel(const float* __restrict__ x,
                      const float* __restrict__ sigma,
                      const float* __restrict__ cvec,
                      const float* __restrict__ W1,
                      const float* __restrict__ b1,
                      const float* __restrict__ W2,
                      const float* __restrict__ b2,
                      const float* __restrict__ W3,
                      const float* __restrict__ b3,
                      const int*   __restrict__ cent,
                      float* __restrict__ out,
                      int write_iidd)
{
    extern __shared__ __align__(16) char dsm[];
    float*    f32all = (float*)dsm;
    unsigned* h2all  = (unsigned*)(dsm + 8 * F32_PER_WARP * 4);

    __shared__ float b1cs[DH];
    __shared__ int   cy0s, cx0s;

    const int tid  = threadIdx.x;
    const int wid  = tid >> 5;
    const int lane = tid & 31;
    const int g_   = lane >> 2;
    const int c_   = lane & 3;
    const int cid  = blockIdx.y;

    if (tid < DH) {
        float acc = b1[tid];
        #pragma unroll
        for (int e = 0; e < NE; e++)
            acc -= cvec[cid * NE + e] * W1[e * DH + tid];
        b1cs[tid] = acc;
    }
    if (tid == 0) {
        int cy = cent[cid * 2 + 0];
        int cx = cent[cid * 2 + 1];
        cy = min(max(cy, HALF), IMG_H - HALF);
        cx = min(max(cx, HALF), IMG_W - HALF);
        cy0s = cy - HALF;
        cx0s = cx - HALF;
    }
    __syncthreads();

    const int cy0 = cy0s, cx0 = cx0s;

    float*    fst = f32all + wid * F32_PER_WARP;
    unsigned* fw  = h2all  + wid * H2_PER_WARP;
    const unsigned fst_sa = (unsigned)__cvta_generic_to_shared(fst);

    const int gy_base = blockIdx.x * 64 + wid;   // rows gy_base + 8r

    // ---- async stage of row r into buf b (register-free) ----
    auto stage = [&](int r, int b) {
        const long roff = (long)(cy0 + gy_base + 8 * r) * IMG_W + cx0 + lane;
        const unsigned dbase = fst_sa + (b * F32_PER_BUF + lane) * 4;
        #pragma unroll
        for (int p = 0; p < 7; p++) {
            const float* src = ((p < NE) ? (x + p * IMG_HW) : sigma) + roff;
            #pragma unroll
            for (int q = 0; q < 4; q++)
                cp4(dbase + (p * PADF + q * 32) * 4, src + q * 32);
        }
        asm volatile("cp.async.commit_group;" ::: "memory");
    };
    // ---- pack staged f32 row (buf b) into packed-h2 buffer ----
    auto pack = [&](int b) {
        const float* fb = fst + b * F32_PER_BUF;
        #pragma unroll
        for (int p2 = 0; p2 < 4; p2++) {
            #pragma unroll
            for (int q = 0; q < 4; q++) {
                int col = q * 32 + lane;
                float lo = fb[(2 * p2) * PADF + col];
                float hi = (p2 < 3) ? fb[(2 * p2 + 1) * PADF + col] : 0.0f;
                fw[p2 * PADW + col] = cvt2h(lo, hi);
            }
        }
    };

    // prologue: kick off rows 0 and 1, load weights underneath
    stage(0, 0);
    stage(1, 1);

    // ---- weight fragments (packed f16x2), loaded once per block ----
    unsigned w1f[2], bias1h[2];
    #pragma unroll
    for (int t = 0; t < 2; t++) {
        int n = 8 * t + g_;
        float w0  = W1[(2 * c_) * DH + n];
        float w1v = (2 * c_ + 1 < NF) ? W1[(2 * c_ + 1) * DH + n] : 0.0f;
        w1f[t] = cvt2h(w0, w1v);
        bias1h[t] = cvt2h(b1cs[8 * t + 2 * c_], b1cs[8 * t + 2 * c_ + 1]);
    }
    unsigned w2f[2][2], bias2h[2];
    #pragma unroll
    for (int t = 0; t < 2; t++) {
        int n = 8 * t + g_;
        w2f[t][0] = cvt2h(W2[(2 * c_)     * DH + n], W2[(2 * c_ + 1) * DH + n]);
        w2f[t][1] = cvt2h(W2[(2 * c_ + 8) * DH + n], W2[(2 * c_ + 9) * DH + n]);
        bias2h[t] = cvt2h(b2[8 * t + 2 * c_], b2[8 * t + 2 * c_ + 1]);
    }
    unsigned w3f[2];
    w3f[0] = cvt2h(W3[2 * c_],     W3[2 * c_ + 1]);
    w3f[1] = cvt2h(W3[2 * c_ + 8], W3[2 * c_ + 9]);
    const float b3v = b3[0];

    // row 0 ready?
    asm volatile("cp.async.wait_group 1;" ::: "memory");
    pack(0);
    __syncwarp();

    const unsigned* fp = fw + c_ * PADW + 4 * g_;

    for (int r = 0; r < ROWS_PER_WARP; r++) {
        const int gy  = gy_base + 8 * r;
        const int row = cy0 + gy;
        const long rowstart = (long)cid * PX_PER_C + (long)gy * WS;
        float* oplane = out + rowstart + 4 * g_ + c_;

        // software pipeline within the row
        uint4 av = *(const uint4*)(fp);

        #pragma unroll
        for (int it = 0; it < 4; it++) {
            const int o = it * 32;
            uint4 cur = av;
            if (it < 3) av = *(const uint4*)(fp + o + 32);

            // ===== tile A =====
            unsigned d1a[2][2];
            #pragma unroll
            for (int t = 0; t < 2; t++)
                mma8h(d1a[t][0], d1a[t][1], cur.x, cur.y, w1f[t], bias1h[t], bias1h[t]);
            unsigned A0 = max2z(d1a[0][0]), A1 = max2z(d1a[0][1]);
            unsigned A2 = max2z(d1a[1][0]), A3 = max2z(d1a[1][1]);

            unsigned d2a[2][2];
            #pragma unroll
            for (int t = 0; t < 2; t++)
                mma16h(d2a[t][0], d2a[t][1], A0, A1, A2, A3,
                       w2f[t][0], w2f[t][1], bias2h[t], bias2h[t]);
            unsigned Ba0 = max2z(d2a[0][0]), Ba1 = max2z(d2a[0][1]);
            unsigned Ba2 = max2z(d2a[1][0]), Ba3 = max2z(d2a[1][1]);

            float d3a[4];
            mma16f(d3a[0], d3a[1], d3a[2], d3a[3],
                   Ba0, Ba1, Ba2, Ba3, w3f[0], w3f[1],
                   b3v, b3v, b3v, b3v);

            // ===== tile B =====
            unsigned d1b[2][2];
            #pragma unroll
            for (int t = 0; t < 2; t++)
                mma8h(d1b[t][0], d1b[t][1], cur.z, cur.w, w1f[t], bias1h[t], bias1h[t]);
            unsigned C0 = max2z(d1b[0][0]), C1 = max2z(d1b[0][1]);
            unsigned C2 = max2z(d1b[1][0]), C3 = max2z(d1b[1][1]);

            unsigned d2b[2][2];
            #pragma unroll
            for (int t = 0; t < 2; t++)
                mma16h(d2b[t][0], d2b[t][1], C0, C1, C2, C3,
                       w2f[t][0], w2f[t][1], bias2h[t], bias2h[t]);
            unsigned Bb0 = max2z(d2b[0][0]), Bb1 = max2z(d2b[0][1]);
            unsigned Bb2 = max2z(d2b[1][0]), Bb3 = max2z(d2b[1][1]);

            float d3b[4];
            mma16f(d3b[0], d3b[1], d3b[2], d3b[3],
                   Bb0, Bb1, Bb2, Bb3, w3f[0], w3f[1],
                   b3v, b3v, b3v, b3v);

            // all-lane sigmoid + coalesced STG.32
            float z0 = (c_ & 2) ? d3b[0] : d3a[0];
            float z1 = (c_ & 2) ? d3b[2] : d3a[2];
            float z  = (c_ & 1) ? z1 : z0;
            oplane[o] = __fdividef(1.0f, 1.0f + __expf(-z));
        }

        // iidd: pure index math, three coalesced STG.128 per row
        if (write_iidd) {
            const float fcid = (float)cid;
            const float frow = (float)row;
            const float fc0  = (float)(cx0 + 4 * lane);
            float4 vc = make_float4(fcid, fcid, fcid, fcid);
            float4 vr = make_float4(frow, frow, frow, frow);
            float4 vx = make_float4(fc0, fc0 + 1.0f, fc0 + 2.0f, fc0 + 3.0f);
            *(float4*)(out + PROB_ELEMS      + rowstart + 4 * lane) = vc;
            *(float4*)(out + 2L * PROB_ELEMS + rowstart + 4 * lane) = vr;
            *(float4*)(out + 3L * PROB_ELEMS + rowstart + 4 * lane) = vx;
        }

        if (r < ROWS_PER_WARP - 1) {
            __syncwarp();                        // warp done reading h2buf
            if (r < ROWS_PER_WARP - 2)
                stage(r + 2, r & 1);             // kick row r+2 into freed buffer
            if (r < ROWS_PER_WARP - 2)
                asm volatile("cp.async.wait_group 1;" ::: "memory");
            else
                asm volatile("cp.async.wait_group 0;" ::: "memory");
            pack((r + 1) & 1);                   // row r+1 -> h2buf
            __syncwarp();
        }
    }
}

extern "C" void kernel_launch(void* const* d_in, const int* in_sizes, int n_in,
                              void* d_out, int out_size)
{
    const float* x     = (const float*)d_in[0];
    const float* sigma = (const float*)d_in[1];
    const float* cvec  = (const float*)d_in[2];
    const float* W1    = (const float*)d_in[3];
    const float* b1    = (const float*)d_in[4];
    const float* W2    = (const float*)d_in[5];
    const float* b2    = (const float*)d_in[6];
    const float* W3    = (const float*)d_in[7];
    const float* b3    = (const float*)d_in[8];
    const int*   cent  = (const int*)d_in[9];
    float* out = (float*)d_out;

    int write_iidd = (out_size >= 4 * PROB_ELEMS) ? 1 : 0;

    static int smem_set = 0;
    if (!smem_set) {
        cudaFuncSetAttribute(instanseg_kernel,
                             cudaFuncAttributeMaxDynamicSharedMemorySize,
                             DSM_BYTES);
        smem_set = 1;
    }

    dim3 grid(BLOCKS_X, NC);
    instanseg_kernel<<<grid, THREADS, DSM_BYTES>>>(x, sigma, cvec, W1, b1, W2, b2,
                                                   W3, b3, cent, out, write_iidd);
}

// round 16
// speedup vs baseline: 1.1496x; 1.1496x over previous
#include <cuda_runtime.h>
#include <cuda_fp16.h>

#define IMG_H 1024
#define IMG_W 1024
#define IMG_HW (IMG_H * IMG_W)
#define WS 128
#define HALF 64
#define NE 6
#define NF 7
#define DH 16
#define NC 512
#define PX_PER_C (WS * WS)
#define PROB_ELEMS (NC * PX_PER_C)

#define THREADS 256          // 8 warps; each warp owns one window row
#define BLOCKS_X 16
#define PADW 136             // half2 words per pair-plane; conflict-free LDS.128

// raw-weight smem layout
#define RW_W1 0              // 112 floats (7x16)
#define RW_W2 112            // 256 floats (16x16)
#define RW_B2 368            // 16
#define RW_W3 384            // 16
#define RW_B3 400            // 1
#define RW_TOT 401

// pack two f32 -> f16x2 (rn); first arg lands in the LOW half
__device__ __forceinline__ unsigned cvt2h(float lo, float hi) {
    unsigned r; asm("cvt.rn.f16x2.f32 %0, %1, %2;" : "=r"(r) : "f"(hi), "f"(lo)); return r;
}
__device__ __forceinline__ unsigned max2z(unsigned v) {
    unsigned r; asm("max.f16x2 %0, %1, %2;" : "=r"(r) : "r"(v), "r"(0u)); return r;
}
// m16n8k8, all-f16
__device__ __forceinline__ void mma8h(unsigned& d0, unsigned& d1,
                                      unsigned a0, unsigned a1,
                                      unsigned b0,
                                      unsigned c0, unsigned c1) {
    asm volatile(
        "mma.sync.aligned.m16n8k8.row.col.f16.f16.f16.f16 "
        "{%0,%1}, {%2,%3}, {%4}, {%5,%6};"
        : "=r"(d0), "=r"(d1)
        : "r"(a0), "r"(a1), "r"(b0), "r"(c0), "r"(c1));
}
// m16n8k16, all-f16
__device__ __forceinline__ void mma16h(unsigned& d0, unsigned& d1,
                                       unsigned a0, unsigned a1, unsigned a2, unsigned a3,
                                       unsigned b0, unsigned b1,
                                       unsigned c0, unsigned c1) {
    asm volatile(
        "mma.sync.aligned.m16n8k16.row.col.f16.f16.f16.f16 "
        "{%0,%1}, {%2,%3,%4,%5}, {%6,%7}, {%8,%9};"
        : "=r"(d0), "=r"(d1)
        : "r"(a0), "r"(a1), "r"(a2), "r"(a3), "r"(b0), "r"(b1), "r"(c0), "r"(c1));
}
// m16n8k16, f16 in, f32 accumulate (final layer)
__device__ __forceinline__ void mma16f(float& d0, float& d1, float& d2, float& d3,
                                       unsigned a0, unsigned a1, unsigned a2, unsigned a3,
                                       unsigned b0, unsigned b1,
                                       float c0, float c1, float c2, float c3) {
    asm volatile(
        "mma.sync.aligned.m16n8k16.row.col.f32.f16.f16.f32 "
        "{%0,%1,%2,%3}, {%4,%5,%6,%7}, {%8,%9}, {%10,%11,%12,%13};"
        : "=f"(d0), "=f"(d1), "=f"(d2), "=f"(d3)
        : "r"(a0), "r"(a1), "r"(a2), "r"(a3), "r"(b0), "r"(b1),
          "f"(c0), "f"(c1), "f"(c2), "f"(c3));
}

__global__ __launch_bounds__(THREADS, 4)
void instanseg_kernel(const float* __restrict__ x,
                      const float* __restrict__ sigma,
                      const float* __restrict__ cvec,
                      const float* __restrict__ W1,
                      const float* __restrict__ b1,
                      const float* __restrict__ W2,
                      const float* __restrict__ b2,
                      const float* __restrict__ W3,
                      const float* __restrict__ b3,
                      const int*   __restrict__ cent,
                      float* __restrict__ out,
                      int write_iidd)
{
    __shared__ float b1cs[DH];                             // b1 - c[cid] @ W1[0:6]
    __shared__ float wraw[RW_TOT];                         // coalesced raw weights
    __shared__ __align__(16) unsigned h2buf[8][4 * PADW];  // [warp][pair][px] half2
    __shared__ int cy0s, cx0s;

    const int tid  = threadIdx.x;
    const int wid  = tid >> 5;
    const int lane = tid & 31;
    const int g_   = lane >> 2;
    const int c_   = lane & 3;
    const int cid  = blockIdx.y;

    // ---- coalesced raw-weight staging (the prologue fix) ----
    if (tid < NF * DH)       wraw[RW_W1 + tid] = W1[tid];
    wraw[RW_W2 + tid >= RW_W2 && tid < DH * DH ? RW_W2 + tid : RW_W2] = wraw[RW_W2]; // no-op guard (avoid compiler warning pattern)
    if (tid < DH * DH)       wraw[RW_W2 + tid] = W2[tid];
    if (tid < DH) {
        wraw[RW_B2 + tid] = b2[tid];
        wraw[RW_W3 + tid] = W3[tid];
        float acc = b1[tid];
        #pragma unroll
        for (int e = 0; e < NE; e++)
            acc -= cvec[cid * NE + e] * W1[e * DH + tid];
        b1cs[tid] = acc;
    }
    if (tid == 0) {
        wraw[RW_B3] = b3[0];
        int cy = cent[cid * 2 + 0];
        int cx = cent[cid * 2 + 1];
        cy = min(max(cy, HALF), IMG_H - HALF);
        cx = min(max(cx, HALF), IMG_W - HALF);
        cy0s = cy - HALF;
        cx0s = cx - HALF;
    }
    __syncthreads();

    const int cy0 = cy0s, cx0 = cx0s;

    // ---- weight fragments built from SMEM (cheap scattered LDS) ----
    unsigned w1f[2], bias1h[2];
    #pragma unroll
    for (int t = 0; t < 2; t++) {
        int n = 8 * t + g_;
        float w0  = wraw[RW_W1 + (2 * c_) * DH + n];
        float w1v = (2 * c_ + 1 < NF) ? wraw[RW_W1 + (2 * c_ + 1) * DH + n] : 0.0f;
        w1f[t] = cvt2h(w0, w1v);
        bias1h[t] = cvt2h(b1cs[8 * t + 2 * c_], b1cs[8 * t + 2 * c_ + 1]);
    }
    unsigned w2f[2][2], bias2h[2];
    #pragma unroll
    for (int t = 0; t < 2; t++) {
        int n = 8 * t + g_;
        w2f[t][0] = cvt2h(wraw[RW_W2 + (2 * c_)     * DH + n],
                          wraw[RW_W2 + (2 * c_ + 1) * DH + n]);
        w2f[t][1] = cvt2h(wraw[RW_W2 + (2 * c_ + 8) * DH + n],
                          wraw[RW_W2 + (2 * c_ + 9) * DH + n]);
        bias2h[t] = cvt2h(wraw[RW_B2 + 8 * t + 2 * c_],
                          wraw[RW_B2 + 8 * t + 2 * c_ + 1]);
    }
    unsigned w3f[2];
    w3f[0] = cvt2h(wraw[RW_W3 + 2 * c_],     wraw[RW_W3 + 2 * c_ + 1]);
    w3f[1] = cvt2h(wraw[RW_W3 + 2 * c_ + 8], wraw[RW_W3 + 2 * c_ + 9]);
    const float b3v = wraw[RW_B3];

    // ---- stage this warp's row as pre-packed half2 feature pairs ----
    const int gy  = blockIdx.x * 8 + wid;
    const int row = cy0 + gy;
    unsigned* fw = h2buf[wid];
    {
        const long roff = (long)row * IMG_W + cx0;
        #pragma unroll
        for (int p = 0; p < 3; p++) {
            const float* f0 = x + (2 * p)     * IMG_HW + roff;
            const float* f1 = x + (2 * p + 1) * IMG_HW + roff;
            #pragma unroll
            for (int q = 0; q < 4; q++) {
                int col = q * 32 + lane;
                fw[p * PADW + col] = cvt2h(f0[col], f1[col]);
            }
        }
        const float* fs = sigma + roff;
        #pragma unroll
        for (int q = 0; q < 4; q++) {
            int col = q * 32 + lane;
            fw[3 * PADW + col] = cvt2h(fs[col], 0.0f);
        }
    }
    __syncwarp();

    const long rowstart = (long)cid * PX_PER_C + (long)gy * WS;
    float* oplane = out + rowstart + 4 * g_ + c_;

    // two-tile pixel permutation within each 32-px group:
    //   tile A: row g_ <-> px o+4g_,   row g_+8 <-> px o+4g_+1
    //   tile B: row g_ <-> px o+4g_+2, row g_+8 <-> px o+4g_+3
    const unsigned* fp = fw + c_ * PADW + 4 * g_;

    // software pipeline: prefetch iter-0 operands
    uint4 av = *(const uint4*)(fp);

    #pragma unroll
    for (int it = 0; it < 4; it++) {
        const int o = it * 32;
        uint4 cur = av;
        if (it < 3) av = *(const uint4*)(fp + o + 32);

        // ===== tile A =====
        unsigned d1a[2][2];
        #pragma unroll
        for (int t = 0; t < 2; t++)
            mma8h(d1a[t][0], d1a[t][1], cur.x, cur.y, w1f[t], bias1h[t], bias1h[t]);
        unsigned A0 = max2z(d1a[0][0]), A1 = max2z(d1a[0][1]);
        unsigned A2 = max2z(d1a[1][0]), A3 = max2z(d1a[1][1]);

        unsigned d2a[2][2];
        #pragma unroll
        for (int t = 0; t < 2; t++)
            mma16h(d2a[t][0], d2a[t][1], A0, A1, A2, A3,
                   w2f[t][0], w2f[t][1], bias2h[t], bias2h[t]);
        unsigned Ba0 = max2z(d2a[0][0]), Ba1 = max2z(d2a[0][1]);
        unsigned Ba2 = max2z(d2a[1][0]), Ba3 = max2z(d2a[1][1]);

        float d3a[4];
        mma16f(d3a[0], d3a[1], d3a[2], d3a[3],
               Ba0, Ba1, Ba2, Ba3, w3f[0], w3f[1],
               b3v, b3v, b3v, b3v);

        // ===== tile B =====
        unsigned d1b[2][2];
        #pragma unroll
        for (int t = 0; t < 2; t++)
            mma8h(d1b[t][0], d1b[t][1], cur.z, cur.w, w1f[t], bias1h[t], bias1h[t]);
        unsigned C0 = max2z(d1b[0][0]), C1 = max2z(d1b[0][1]);
        unsigned C2 = max2z(d1b[1][0]), C3 = max2z(d1b[1][1]);

        unsigned d2b[2][2];
        #pragma unroll
        for (int t = 0; t < 2; t++)
            mma16h(d2b[t][0], d2b[t][1], C0, C1, C2, C3,
                   w2f[t][0], w2f[t][1], bias2h[t], bias2h[t]);
        unsigned Bb0 = max2z(d2b[0][0]), Bb1 = max2z(d2b[0][1]);
        unsigned Bb2 = max2z(d2b[1][0]), Bb3 = max2z(d2b[1][1]);

        float d3b[4];
        mma16f(d3b[0], d3b[1], d3b[2], d3b[3],
               Bb0, Bb1, Bb2, Bb3, w3f[0], w3f[1],
               b3v, b3v, b3v, b3v);

        // all-lane sigmoid + coalesced STG.32
        float z0 = (c_ & 2) ? d3b[0] : d3a[0];
        float z1 = (c_ & 2) ? d3b[2] : d3a[2];
        float z  = (c_ & 1) ? z1 : z0;
        oplane[o] = __fdividef(1.0f, 1.0f + __expf(-z));
    }

    // ---- iidd: pure index math, three coalesced STG.128 per row ----
    if (write_iidd) {
        const float fcid = (float)cid;
        const float frow = (float)row;
        const float fc0  = (float)(cx0 + 4 * lane);
        float4 vc = make_float4(fcid, fcid, fcid, fcid);
        float4 vr = make_float4(frow, frow, frow, frow);
        float4 vx = make_float4(fc0, fc0 + 1.0f, fc0 + 2.0f, fc0 + 3.0f);
        *(float4*)(out + PROB_ELEMS      + rowstart + 4 * lane) = vc;
        *(float4*)(out + 2L * PROB_ELEMS + rowstart + 4 * lane) = vr;
        *(float4*)(out + 3L * PROB_ELEMS + rowstart + 4 * lane) = vx;
    }
}

extern "C" void kernel_launch(void* const* d_in, const int* in_sizes, int n_in,
                              void* d_out, int out_size)
{
    const float* x     = (const float*)d_in[0];
    const float* sigma = (const float*)d_in[1];
    const float* cvec  = (const float*)d_in[2];
    const float* W1    = (const float*)d_in[3];
    const float* b1    = (const float*)d_in[4];
    const float* W2    = (const float*)d_in[5];
    const float* b2    = (const float*)d_in[6];
    const float* W3    = (const float*)d_in[7];
    const float* b3    = (const float*)d_in[8];
    const int*   cent  = (const int*)d_in[9];
    float* out = (float*)d_out;

    int write_iidd = (out_size >= 4 * PROB_ELEMS) ? 1 : 0;

    dim3 grid(BLOCKS_X, NC);
    instanseg_kernel<<<grid, THREADS>>>(x, sigma, cvec, W1, b1, W2, b2, W3, b3,
                                        cent, out, write_iidd);
}